// round 2
// baseline (speedup 1.0000x reference)
#include <cuda_runtime.h>
#include <cuda_bf16.h>

// Problem constants (from reference: B=64, N=1000, K=128)
static constexpr int BATCH = 64;
static constexpr int NN    = 1000;
static constexpr int KK    = 128;

// Scratch for per-batch partial sums (no device allocation allowed).
__device__ float g_partials[BATCH];

// Load index t from a buffer whose dtype (int32 vs int64) we detect at runtime.
// Detection: interpret as int64; valid iff ALL block threads see in-range values.
__device__ __forceinline__ int load_index(const void* buf, int t, int use_i64)
{
    if (use_i64) return (int)((const long long*)buf)[t];
    return ((const int*)buf)[t];
}

// One block per batch element. 128 threads, one (row,col) pair per thread.
// Dedupe pairs (set semantics), gather the two floats, square-diff, reduce.
__global__ void masked_loss_partial(const float* __restrict__ y_true,
                                    const float* __restrict__ y_pred,
                                    const void* __restrict__ rows,
                                    const void* __restrict__ cols)
{
    __shared__ int sr[KK];
    __shared__ int sc[KK];
    __shared__ float warp_sums[4];

    const int t = threadIdx.x;          // 0..127
    const int b = blockIdx.x;           // 0..63

    // --- dtype detection (int64 claimed by reference, but JAX x64-off => int32) ---
    const long long r64 = ((const long long*)rows)[t];
    const long long c64 = ((const long long*)cols)[t];
    const int in_range = (r64 >= 0 && r64 < NN && c64 >= 0 && c64 < NN) ? 1 : 0;
    const int use_i64 = __syncthreads_and(in_range);

    sr[t] = load_index(rows, t, use_i64);
    sc[t] = load_index(cols, t, use_i64);
    __syncthreads();

    const int r = sr[t];
    const int c = sc[t];

    // Set semantics: keep only the first occurrence of each (r,c) pair.
    bool keep = true;
    for (int j = 0; j < t; ++j) {
        if (sr[j] == r && sc[j] == c) { keep = false; break; }
    }

    float acc = 0.0f;
    if (keep) {
        const size_t base = (size_t)b * NN * NN + (size_t)r * NN + (size_t)c;
        const float d = y_true[base] - y_pred[base];
        acc = d * d;
    }

    // Warp reduce (4 warps)
    #pragma unroll
    for (int off = 16; off > 0; off >>= 1)
        acc += __shfl_xor_sync(0xffffffffu, acc, off);

    if ((t & 31) == 0) warp_sums[t >> 5] = acc;
    __syncthreads();

    if (t == 0) {
        g_partials[b] = warp_sums[0] + warp_sums[1] + warp_sums[2] + warp_sums[3];
    }
}

// Deterministic final reduction of 64 partials -> scalar output.
__global__ void masked_loss_finalize(float* __restrict__ out)
{
    __shared__ float warp_sums[2];
    const int t = threadIdx.x;          // 0..63
    float v = g_partials[t];

    #pragma unroll
    for (int off = 16; off > 0; off >>= 1)
        v += __shfl_xor_sync(0xffffffffu, v, off);

    if ((t & 31) == 0) warp_sums[t >> 5] = v;
    __syncthreads();

    if (t == 0) out[0] = warp_sums[0] + warp_sums[1];
}

extern "C" void kernel_launch(void* const* d_in, const int* in_sizes, int n_in,
                              void* d_out, int out_size)
{
    const float* y_true = (const float*)d_in[0];
    const float* y_pred = (const float*)d_in[1];
    const void*  rows   = d_in[2];
    const void*  cols   = d_in[3];
    float* out = (float*)d_out;

    masked_loss_partial<<<BATCH, KK>>>(y_true, y_pred, rows, cols);
    masked_loss_finalize<<<1, BATCH>>>(out);
}